// round 11
// baseline (speedup 1.0000x reference)
#include <cuda_runtime.h>
#include <cuda_bf16.h>
#include <math.h>

// Problem constants
#define BB    16
#define LL    128
#define DD    512
#define HH    256
#define TAGS  45
#define LP1   129   // L + 1 (root prepended)

#define TM    8     // rows per block in kernel 1
#define GI    8     // i-rows per block in kernel 2

typedef unsigned long long ull;

// Scratch (device globals — no allocation allowed)
__device__ float g_ha[BB * LL * HH];     // hidden @ Wa           (2 MB)
__device__ float g_hb[BB * LL * HH];     // hidden @ Wb           (2 MB)
__device__ float g_hbroot[HH];           // root @ Wb
__device__ float g_ce[BB * LL];          // per-token (arc_ce + lab_ce) * mask

// ---- packed f32x2 helpers (sm_103a FFMA2 path, PTX-only) --------------------
__device__ __forceinline__ ull pack2(float lo, float hi) {
    ull r;
    asm("mov.b64 %0, {%1, %2};" : "=l"(r) : "f"(lo), "f"(hi));
    return r;
}
__device__ __forceinline__ void fma2(ull& d, ull a, ull b) {
    asm("fma.rn.f32x2 %0, %1, %2, %0;" : "+l"(d) : "l"(a), "l"(b));
}
__device__ __forceinline__ float hsum2(ull v) {
    float lo, hi;
    asm("mov.b64 {%0, %1}, %2;" : "=f"(lo), "=f"(hi) : "l"(v));
    return lo + hi;
}

// ---------------------------------------------------------------------------
// Kernel 1: hidden = relu(X @ W1 + b1); ha = hidden @ Wa; hb = hidden @ Wb
// Thread layout: tid = rh*128 + cp.  cp -> column pair (h0 = 2*cp), rh -> row
// half (rows rh*4 .. rh*4+3).  All threads of a row-half read the SAME smem
// x/h vector (broadcast), weights via coalesced LDG.64, accumulation in
// packed f32x2 along the K dimension (even/odd partial sums, hadd at end).
// Block 256 (last) computes g_hbroot = root @ Wb.
// ---------------------------------------------------------------------------
__global__ __launch_bounds__(256) void k1_proj(
    const float* __restrict__ x,     // [B,L,D]
    const float* __restrict__ W1,    // [D,H]
    const float* __restrict__ b1,    // [H]
    const float* __restrict__ root,  // [H]
    const float* __restrict__ Wp)    // [2H,H]
{
    if (blockIdx.x == (BB * LL) / TM) {
        const int h = threadIdx.x;
        float acc = 0.f;
        #pragma unroll 4
        for (int k = 0; k < HH; k++)
            acc = fmaf(root[k], Wp[(HH + k) * HH + h], acc);
        g_hbroot[h] = acc;
        return;
    }

    __shared__ __align__(16) float xs[TM][DD];   // 16 KB
    __shared__ __align__(16) float hs[TM][HH];   // 8 KB

    const int tid = threadIdx.x;
    const int cp  = tid & 127;        // column pair index 0..127
    const int rh  = tid >> 7;         // row half 0/1
    const int h0  = cp * 2;
    const int r0  = rh * 4;
    const int row0 = blockIdx.x * TM;

    // Load X tile (coalesced float4)
    {
        const float4* xg = reinterpret_cast<const float4*>(x + (size_t)row0 * DD);
        float4* xsv = reinterpret_cast<float4*>(&xs[0][0]);
        #pragma unroll
        for (int i = tid; i < TM * DD / 4; i += 256)
            xsv[i] = xg[i];
    }
    __syncthreads();

    // ---- Stage 1: hidden = relu(X @ W1 + b1), cols (h0, h0+1), rows r0..r0+3
    {
        const float2* w1v = reinterpret_cast<const float2*>(W1) + (h0 >> 1);
        ull acc[4][2];
        #pragma unroll
        for (int r = 0; r < 4; r++) { acc[r][0] = 0ull; acc[r][1] = 0ull; }

        #pragma unroll 2
        for (int d = 0; d < DD; d += 4) {
            const float2 w0 = w1v[(d + 0) * (HH / 2)];
            const float2 w1 = w1v[(d + 1) * (HH / 2)];
            const float2 w2 = w1v[(d + 2) * (HH / 2)];
            const float2 w3 = w1v[(d + 3) * (HH / 2)];
            const ull pc0_01 = pack2(w0.x, w1.x);   // col0, d-pair (d, d+1)
            const ull pc1_01 = pack2(w0.y, w1.y);   // col1
            const ull pc0_23 = pack2(w2.x, w3.x);
            const ull pc1_23 = pack2(w2.y, w3.y);
            #pragma unroll
            for (int r = 0; r < 4; r++) {
                const float4 xv = *reinterpret_cast<const float4*>(&xs[r0 + r][d]);
                const ull x01 = pack2(xv.x, xv.y);
                const ull x23 = pack2(xv.z, xv.w);
                fma2(acc[r][0], x01, pc0_01);
                fma2(acc[r][1], x01, pc1_01);
                fma2(acc[r][0], x23, pc0_23);
                fma2(acc[r][1], x23, pc1_23);
            }
        }
        const float bias0 = b1[h0];
        const float bias1 = b1[h0 + 1];
        #pragma unroll
        for (int r = 0; r < 4; r++) {
            float2 hv;
            hv.x = fmaxf(hsum2(acc[r][0]) + bias0, 0.f);
            hv.y = fmaxf(hsum2(acc[r][1]) + bias1, 0.f);
            *reinterpret_cast<float2*>(&hs[r0 + r][h0]) = hv;
        }
    }
    __syncthreads();

    // ---- Stage 2: ha = hidden @ Wa, hb = hidden @ Wb (same thread mapping)
    {
        const float2* wav = reinterpret_cast<const float2*>(Wp) + (h0 >> 1);
        const float2* wbv = reinterpret_cast<const float2*>(Wp + (size_t)HH * HH) + (h0 >> 1);

        ull aa[4][2], ab[4][2];
        #pragma unroll
        for (int r = 0; r < 4; r++) {
            aa[r][0] = 0ull; aa[r][1] = 0ull;
            ab[r][0] = 0ull; ab[r][1] = 0ull;
        }

        for (int k = 0; k < HH; k += 4) {
            const float2 a0 = wav[(k + 0) * (HH / 2)];
            const float2 a1 = wav[(k + 1) * (HH / 2)];
            const float2 a2 = wav[(k + 2) * (HH / 2)];
            const float2 a3 = wav[(k + 3) * (HH / 2)];
            const float2 b0 = wbv[(k + 0) * (HH / 2)];
            const float2 b1v = wbv[(k + 1) * (HH / 2)];
            const float2 b2 = wbv[(k + 2) * (HH / 2)];
            const float2 b3 = wbv[(k + 3) * (HH / 2)];

            const ull pa0_01 = pack2(a0.x, a1.x);
            const ull pa1_01 = pack2(a0.y, a1.y);
            const ull pa0_23 = pack2(a2.x, a3.x);
            const ull pa1_23 = pack2(a2.y, a3.y);
            const ull pb0_01 = pack2(b0.x, b1v.x);
            const ull pb1_01 = pack2(b0.y, b1v.y);
            const ull pb0_23 = pack2(b2.x, b3.x);
            const ull pb1_23 = pack2(b2.y, b3.y);

            #pragma unroll
            for (int r = 0; r < 4; r++) {
                const float4 hv = *reinterpret_cast<const float4*>(&hs[r0 + r][k]);
                const ull h01 = pack2(hv.x, hv.y);
                const ull h23 = pack2(hv.z, hv.w);
                fma2(aa[r][0], h01, pa0_01);
                fma2(aa[r][1], h01, pa1_01);
                fma2(aa[r][0], h23, pa0_23);
                fma2(aa[r][1], h23, pa1_23);
                fma2(ab[r][0], h01, pb0_01);
                fma2(ab[r][1], h01, pb1_01);
                fma2(ab[r][0], h23, pb0_23);
                fma2(ab[r][1], h23, pb1_23);
            }
        }

        #pragma unroll
        for (int r = 0; r < 4; r++) {
            const size_t row = (size_t)(row0 + r0 + r);
            float2 va, vb;
            va.x = hsum2(aa[r][0]);  va.y = hsum2(aa[r][1]);
            vb.x = hsum2(ab[r][0]);  vb.y = hsum2(ab[r][1]);
            *reinterpret_cast<float2*>(&g_ha[row * HH + h0]) = va;
            *reinterpret_cast<float2*>(&g_hb[row * HH + h0]) = vb;
        }
    }
}

// ---------------------------------------------------------------------------
// Kernel 2: for each (b, i): arc logits over j=0..128 (computed on the fly),
// arc log-softmax CE; gathered sel = relu(ha_i + hb_{j*} + bp); label logits,
// label log-softmax CE. Writes g_ce[b*L+i] = mask * (arc_ce + lab_ce).
// One block per (b, group of GI=8 i-rows). 256 threads = 8 warps.
// ---------------------------------------------------------------------------
__global__ __launch_bounds__(256) void k2_score(
    const int*   __restrict__ slen,     // [B]
    const int*   __restrict__ darcs,    // [B,L]
    const int*   __restrict__ dlabs,    // [B,L]
    const float* __restrict__ bp,       // [H]
    const float* __restrict__ W_arc,    // [H,1]
    const float* __restrict__ W_lab,    // [H,TAGS]
    const float* __restrict__ b_lab)    // [TAGS]
{
    __shared__ float sha[GI][HH];        // ha rows + bp   (8 KB)
    __shared__ float warc[HH];           // 1 KB
    __shared__ float slog[GI][132];      // arc logits     (~4.2 KB)
    __shared__ float ssel[GI][HH];       // gathered pair repr (8 KB)
    __shared__ float slab[GI][48];       // label logits   (1.5 KB)

    const int t    = threadIdx.x;
    const int w    = t >> 5;
    const int lane = t & 31;

    const int b  = blockIdx.x / (LL / GI);
    const int ig = blockIdx.x % (LL / GI);
    const int i0 = ig * GI;
    const int len = slen[b];

    // Load ha rows (+bp) and W_arc
    warc[t] = W_arc[t];
    #pragma unroll
    for (int r = 0; r < GI; r++)
        sha[r][t] = g_ha[(size_t)(b * LL + i0 + r) * HH + t] + bp[t];
    __syncthreads();

    // ---- Arc logits: warp w handles j = w, w+8, ... ----
    for (int j = w; j < LP1; j += 8) {
        const float* hbj = (j == 0) ? g_hbroot
                                    : &g_hb[(size_t)(b * LL + (j - 1)) * HH];
        float p[GI];
        #pragma unroll
        for (int r = 0; r < GI; r++) p[r] = 0.f;

        #pragma unroll
        for (int t8 = 0; t8 < 8; t8++) {
            const int k = lane + 32 * t8;
            const float hv = hbj[k];
            const float wv = warc[k];
            #pragma unroll
            for (int r = 0; r < GI; r++)
                p[r] = fmaf(fmaxf(sha[r][k] + hv, 0.f), wv, p[r]);
        }
        #pragma unroll
        for (int r = 0; r < GI; r++) {
            float v = p[r];
            #pragma unroll
            for (int off = 16; off; off >>= 1)
                v += __shfl_xor_sync(0xffffffffu, v, off);
            p[r] = v;
        }
        if (lane == 0) {
            #pragma unroll
            for (int r = 0; r < GI; r++) slog[r][j] = p[r];
        }
    }
    __syncthreads();

    // ---- Arc log-softmax: warp w handles row r = w ----
    float arc_ce = 0.f;
    {
        const int r = w;
        float m = -INFINITY;
        for (int jj = lane; jj < LP1; jj += 32) m = fmaxf(m, slog[r][jj]);
        #pragma unroll
        for (int off = 16; off; off >>= 1)
            m = fmaxf(m, __shfl_xor_sync(0xffffffffu, m, off));
        float s = 0.f;
        for (int jj = lane; jj < LP1; jj += 32) s += expf(slog[r][jj] - m);
        #pragma unroll
        for (int off = 16; off; off >>= 1)
            s += __shfl_xor_sync(0xffffffffu, s, off);
        const float lse = m + logf(s);
        const int ja = darcs[b * LL + i0 + r];
        arc_ce = lse - slog[r][ja];
    }

    // ---- Gathered sel = relu(ha + hb[j*] + bp), all threads ----
    #pragma unroll
    for (int r = 0; r < GI; r++) {
        const int ja = darcs[b * LL + i0 + r];
        const float* hbj = (ja == 0) ? g_hbroot
                                     : &g_hb[(size_t)(b * LL + (ja - 1)) * HH];
        ssel[r][t] = fmaxf(sha[r][t] + hbj[t], 0.f);
    }
    __syncthreads();

    // ---- Label logits: 360 dots of length 256 spread over threads ----
    for (int q = t; q < GI * TAGS; q += 256) {
        const int r = q / TAGS;
        const int tag = q % TAGS;
        float a = b_lab[tag];
        #pragma unroll 4
        for (int k = 0; k < HH; k++)
            a = fmaf(ssel[r][k], W_lab[k * TAGS + tag], a);
        slab[r][tag] = a;
    }
    __syncthreads();

    // ---- Label log-softmax: warp w handles row r = w ----
    {
        const int r = w;
        float m = -INFINITY;
        for (int tg = lane; tg < TAGS; tg += 32) m = fmaxf(m, slab[r][tg]);
        #pragma unroll
        for (int off = 16; off; off >>= 1)
            m = fmaxf(m, __shfl_xor_sync(0xffffffffu, m, off));
        float s = 0.f;
        for (int tg = lane; tg < TAGS; tg += 32) s += expf(slab[r][tg] - m);
        #pragma unroll
        for (int off = 16; off; off >>= 1)
            s += __shfl_xor_sync(0xffffffffu, s, off);
        const float lse = m + logf(s);
        const int tl = dlabs[b * LL + i0 + r];
        const float lab_ce = lse - slab[r][tl];

        if (lane == 0) {
            const int i = i0 + r;
            g_ce[b * LL + i] = (i < len) ? (arc_ce + lab_ce) : 0.f;
        }
    }
}

// ---------------------------------------------------------------------------
// Kernel 3: final reduction -> scalar loss
// ---------------------------------------------------------------------------
__global__ __launch_bounds__(256) void k3_reduce(
    const int* __restrict__ slen, float* __restrict__ out)
{
    __shared__ float red[256];
    float s = 0.f;
    for (int i = threadIdx.x; i < BB * LL; i += 256) s += g_ce[i];
    red[threadIdx.x] = s;
    __syncthreads();
    #pragma unroll
    for (int st = 128; st > 0; st >>= 1) {
        if (threadIdx.x < st) red[threadIdx.x] += red[threadIdx.x + st];
        __syncthreads();
    }
    if (threadIdx.x == 0) {
        float denom = 0.f;
        #pragma unroll
        for (int bb = 0; bb < BB; bb++) denom += (float)slen[bb];
        denom = fmaxf(denom, 1.f);
        out[0] = red[0] / denom * 0.5f;
    }
}

// ---------------------------------------------------------------------------
// Input order (metadata.txt):
// 0 contextualized [B,L,D] f32     1 sentence_lengths [B] i32
// 2 desired_arcs [B,L] i32         3 desired_labels [B,L] i32
// 4 W1 [D,H] f32                   5 b1 [H] f32
// 6 root [H] f32                   7 Wp [2H,H] f32
// 8 bp [H] f32                     9 W_arc [H,1] f32
// 10 b_arc [1] f32                 11 W_lab [H,TAGS] f32
// 12 b_lab [TAGS] f32
// ---------------------------------------------------------------------------
extern "C" void kernel_launch(void* const* d_in, const int* in_sizes, int n_in,
                              void* d_out, int out_size)
{
    const float* x     = (const float*)d_in[0];
    const int*   slen  = (const int*)  d_in[1];
    const int*   darcs = (const int*)  d_in[2];
    const int*   dlabs = (const int*)  d_in[3];
    const float* W1    = (const float*)d_in[4];
    const float* b1    = (const float*)d_in[5];
    const float* root  = (const float*)d_in[6];
    const float* Wp    = (const float*)d_in[7];
    const float* bp    = (const float*)d_in[8];
    const float* W_arc = (const float*)d_in[9];
    const float* W_lab = (const float*)d_in[11];
    const float* b_lab = (const float*)d_in[12];
    float* out = (float*)d_out;

    k1_proj <<< (BB * LL) / TM + 1, 256 >>>(x, W1, b1, root, Wp);
    k2_score<<< BB * (LL / GI),     256 >>>(slen, darcs, dlabs, bp, W_arc, W_lab, b_lab);
    k3_reduce<<< 1,                 256 >>>(slen, out);
}

// round 12
// speedup vs baseline: 1.0004x; 1.0004x over previous
#include <cuda_runtime.h>
#include <cuda_bf16.h>
#include <math.h>

// Problem constants
#define BB    16
#define LL    128
#define DD    512
#define HH    256
#define TAGS  45
#define LP1   129   // L + 1 (root prepended)

#define TM    8     // rows per block in kernel 1
#define GI    8     // i-rows per block in kernel 2

typedef unsigned long long ull;

// Scratch (device globals — no allocation allowed)
__device__ float g_ha[BB * LL * HH];     // hidden @ Wa           (2 MB)
__device__ float g_hb[BB * LL * HH];     // hidden @ Wb           (2 MB)
__device__ float g_hbroot[HH];           // root @ Wb
__device__ float g_ce[BB * LL];          // per-token (arc_ce + lab_ce) * mask

// ---- packed f32x2 helpers (sm_103a FFMA2 path, PTX-only) --------------------
__device__ __forceinline__ ull pack2(float lo, float hi) {
    ull r;
    asm("mov.b64 %0, {%1, %2};" : "=l"(r) : "f"(lo), "f"(hi));
    return r;
}
__device__ __forceinline__ void fma2(ull& d, ull a, ull b) {
    asm("fma.rn.f32x2 %0, %1, %2, %0;" : "+l"(d) : "l"(a), "l"(b));
}
__device__ __forceinline__ float hsum2(ull v) {
    float lo, hi;
    asm("mov.b64 {%0, %1}, %2;" : "=f"(lo), "=f"(hi) : "l"(v));
    return lo + hi;
}

// ---------------------------------------------------------------------------
// Kernel 1: hidden = relu(X @ W1 + b1); ha = hidden @ Wa; hb = hidden @ Wb
// Thread layout: tid = rh*128 + cp.  cp -> column pair (h0 = 2*cp), rh -> row
// half (rows rh*4 .. rh*4+3).  All threads of a row-half read the SAME smem
// x/h vector (broadcast), weights via coalesced LDG.64, accumulation in
// packed f32x2 along the K dimension (even/odd partial sums, hadd at end).
// Block 256 (last) computes g_hbroot = root @ Wb.
// ---------------------------------------------------------------------------
__global__ __launch_bounds__(256) void k1_proj(
    const float* __restrict__ x,     // [B,L,D]
    const float* __restrict__ W1,    // [D,H]
    const float* __restrict__ b1,    // [H]
    const float* __restrict__ root,  // [H]
    const float* __restrict__ Wp)    // [2H,H]
{
    if (blockIdx.x == (BB * LL) / TM) {
        const int h = threadIdx.x;
        float acc = 0.f;
        #pragma unroll 4
        for (int k = 0; k < HH; k++)
            acc = fmaf(root[k], Wp[(HH + k) * HH + h], acc);
        g_hbroot[h] = acc;
        return;
    }

    __shared__ __align__(16) float xs[TM][DD];   // 16 KB
    __shared__ __align__(16) float hs[TM][HH];   // 8 KB

    const int tid = threadIdx.x;
    const int cp  = tid & 127;        // column pair index 0..127
    const int rh  = tid >> 7;         // row half 0/1
    const int h0  = cp * 2;
    const int r0  = rh * 4;
    const int row0 = blockIdx.x * TM;

    // Load X tile (coalesced float4)
    {
        const float4* xg = reinterpret_cast<const float4*>(x + (size_t)row0 * DD);
        float4* xsv = reinterpret_cast<float4*>(&xs[0][0]);
        #pragma unroll
        for (int i = tid; i < TM * DD / 4; i += 256)
            xsv[i] = xg[i];
    }
    __syncthreads();

    // ---- Stage 1: hidden = relu(X @ W1 + b1), cols (h0, h0+1), rows r0..r0+3
    {
        const float2* w1v = reinterpret_cast<const float2*>(W1) + (h0 >> 1);
        ull acc[4][2];
        #pragma unroll
        for (int r = 0; r < 4; r++) { acc[r][0] = 0ull; acc[r][1] = 0ull; }

        #pragma unroll 2
        for (int d = 0; d < DD; d += 4) {
            const float2 w0 = w1v[(d + 0) * (HH / 2)];
            const float2 w1 = w1v[(d + 1) * (HH / 2)];
            const float2 w2 = w1v[(d + 2) * (HH / 2)];
            const float2 w3 = w1v[(d + 3) * (HH / 2)];
            const ull pc0_01 = pack2(w0.x, w1.x);   // col0, d-pair (d, d+1)
            const ull pc1_01 = pack2(w0.y, w1.y);   // col1
            const ull pc0_23 = pack2(w2.x, w3.x);
            const ull pc1_23 = pack2(w2.y, w3.y);
            #pragma unroll
            for (int r = 0; r < 4; r++) {
                const float4 xv = *reinterpret_cast<const float4*>(&xs[r0 + r][d]);
                const ull x01 = pack2(xv.x, xv.y);
                const ull x23 = pack2(xv.z, xv.w);
                fma2(acc[r][0], x01, pc0_01);
                fma2(acc[r][1], x01, pc1_01);
                fma2(acc[r][0], x23, pc0_23);
                fma2(acc[r][1], x23, pc1_23);
            }
        }
        const float bias0 = b1[h0];
        const float bias1 = b1[h0 + 1];
        #pragma unroll
        for (int r = 0; r < 4; r++) {
            float2 hv;
            hv.x = fmaxf(hsum2(acc[r][0]) + bias0, 0.f);
            hv.y = fmaxf(hsum2(acc[r][1]) + bias1, 0.f);
            *reinterpret_cast<float2*>(&hs[r0 + r][h0]) = hv;
        }
    }
    __syncthreads();

    // ---- Stage 2: ha = hidden @ Wa, hb = hidden @ Wb (same thread mapping)
    {
        const float2* wav = reinterpret_cast<const float2*>(Wp) + (h0 >> 1);
        const float2* wbv = reinterpret_cast<const float2*>(Wp + (size_t)HH * HH) + (h0 >> 1);

        ull aa[4][2], ab[4][2];
        #pragma unroll
        for (int r = 0; r < 4; r++) {
            aa[r][0] = 0ull; aa[r][1] = 0ull;
            ab[r][0] = 0ull; ab[r][1] = 0ull;
        }

        for (int k = 0; k < HH; k += 4) {
            const float2 a0 = wav[(k + 0) * (HH / 2)];
            const float2 a1 = wav[(k + 1) * (HH / 2)];
            const float2 a2 = wav[(k + 2) * (HH / 2)];
            const float2 a3 = wav[(k + 3) * (HH / 2)];
            const float2 b0 = wbv[(k + 0) * (HH / 2)];
            const float2 b1v = wbv[(k + 1) * (HH / 2)];
            const float2 b2 = wbv[(k + 2) * (HH / 2)];
            const float2 b3 = wbv[(k + 3) * (HH / 2)];

            const ull pa0_01 = pack2(a0.x, a1.x);
            const ull pa1_01 = pack2(a0.y, a1.y);
            const ull pa0_23 = pack2(a2.x, a3.x);
            const ull pa1_23 = pack2(a2.y, a3.y);
            const ull pb0_01 = pack2(b0.x, b1v.x);
            const ull pb1_01 = pack2(b0.y, b1v.y);
            const ull pb0_23 = pack2(b2.x, b3.x);
            const ull pb1_23 = pack2(b2.y, b3.y);

            #pragma unroll
            for (int r = 0; r < 4; r++) {
                const float4 hv = *reinterpret_cast<const float4*>(&hs[r0 + r][k]);
                const ull h01 = pack2(hv.x, hv.y);
                const ull h23 = pack2(hv.z, hv.w);
                fma2(aa[r][0], h01, pa0_01);
                fma2(aa[r][1], h01, pa1_01);
                fma2(aa[r][0], h23, pa0_23);
                fma2(aa[r][1], h23, pa1_23);
                fma2(ab[r][0], h01, pb0_01);
                fma2(ab[r][1], h01, pb1_01);
                fma2(ab[r][0], h23, pb0_23);
                fma2(ab[r][1], h23, pb1_23);
            }
        }

        #pragma unroll
        for (int r = 0; r < 4; r++) {
            const size_t row = (size_t)(row0 + r0 + r);
            float2 va, vb;
            va.x = hsum2(aa[r][0]);  va.y = hsum2(aa[r][1]);
            vb.x = hsum2(ab[r][0]);  vb.y = hsum2(ab[r][1]);
            *reinterpret_cast<float2*>(&g_ha[row * HH + h0]) = va;
            *reinterpret_cast<float2*>(&g_hb[row * HH + h0]) = vb;
        }
    }
}

// ---------------------------------------------------------------------------
// Kernel 2: for each (b, i): arc logits over j=0..128 (computed on the fly),
// arc log-softmax CE; gathered sel = relu(ha_i + hb_{j*} + bp); label logits,
// label log-softmax CE. Writes g_ce[b*L+i] = mask * (arc_ce + lab_ce).
// One block per (b, group of GI=8 i-rows). 256 threads = 8 warps.
// ---------------------------------------------------------------------------
__global__ __launch_bounds__(256) void k2_score(
    const int*   __restrict__ slen,     // [B]
    const int*   __restrict__ darcs,    // [B,L]
    const int*   __restrict__ dlabs,    // [B,L]
    const float* __restrict__ bp,       // [H]
    const float* __restrict__ W_arc,    // [H,1]
    const float* __restrict__ W_lab,    // [H,TAGS]
    const float* __restrict__ b_lab)    // [TAGS]
{
    __shared__ float sha[GI][HH];        // ha rows + bp   (8 KB)
    __shared__ float warc[HH];           // 1 KB
    __shared__ float slog[GI][132];      // arc logits     (~4.2 KB)
    __shared__ float ssel[GI][HH];       // gathered pair repr (8 KB)
    __shared__ float slab[GI][48];       // label logits   (1.5 KB)

    const int t    = threadIdx.x;
    const int w    = t >> 5;
    const int lane = t & 31;

    const int b  = blockIdx.x / (LL / GI);
    const int ig = blockIdx.x % (LL / GI);
    const int i0 = ig * GI;
    const int len = slen[b];

    // Load ha rows (+bp) and W_arc
    warc[t] = W_arc[t];
    #pragma unroll
    for (int r = 0; r < GI; r++)
        sha[r][t] = g_ha[(size_t)(b * LL + i0 + r) * HH + t] + bp[t];
    __syncthreads();

    // ---- Arc logits: warp w handles j = w, w+8, ... ----
    for (int j = w; j < LP1; j += 8) {
        const float* hbj = (j == 0) ? g_hbroot
                                    : &g_hb[(size_t)(b * LL + (j - 1)) * HH];
        float p[GI];
        #pragma unroll
        for (int r = 0; r < GI; r++) p[r] = 0.f;

        #pragma unroll
        for (int t8 = 0; t8 < 8; t8++) {
            const int k = lane + 32 * t8;
            const float hv = hbj[k];
            const float wv = warc[k];
            #pragma unroll
            for (int r = 0; r < GI; r++)
                p[r] = fmaf(fmaxf(sha[r][k] + hv, 0.f), wv, p[r]);
        }
        #pragma unroll
        for (int r = 0; r < GI; r++) {
            float v = p[r];
            #pragma unroll
            for (int off = 16; off; off >>= 1)
                v += __shfl_xor_sync(0xffffffffu, v, off);
            p[r] = v;
        }
        if (lane == 0) {
            #pragma unroll
            for (int r = 0; r < GI; r++) slog[r][j] = p[r];
        }
    }
    __syncthreads();

    // ---- Arc log-softmax: warp w handles row r = w ----
    float arc_ce = 0.f;
    {
        const int r = w;
        float m = -INFINITY;
        for (int jj = lane; jj < LP1; jj += 32) m = fmaxf(m, slog[r][jj]);
        #pragma unroll
        for (int off = 16; off; off >>= 1)
            m = fmaxf(m, __shfl_xor_sync(0xffffffffu, m, off));
        float s = 0.f;
        for (int jj = lane; jj < LP1; jj += 32) s += expf(slog[r][jj] - m);
        #pragma unroll
        for (int off = 16; off; off >>= 1)
            s += __shfl_xor_sync(0xffffffffu, s, off);
        const float lse = m + logf(s);
        const int ja = darcs[b * LL + i0 + r];
        arc_ce = lse - slog[r][ja];
    }

    // ---- Gathered sel = relu(ha + hb[j*] + bp), all threads ----
    #pragma unroll
    for (int r = 0; r < GI; r++) {
        const int ja = darcs[b * LL + i0 + r];
        const float* hbj = (ja == 0) ? g_hbroot
                                     : &g_hb[(size_t)(b * LL + (ja - 1)) * HH];
        ssel[r][t] = fmaxf(sha[r][t] + hbj[t], 0.f);
    }
    __syncthreads();

    // ---- Label logits: 360 dots of length 256 spread over threads ----
    for (int q = t; q < GI * TAGS; q += 256) {
        const int r = q / TAGS;
        const int tag = q % TAGS;
        float a = b_lab[tag];
        #pragma unroll 4
        for (int k = 0; k < HH; k++)
            a = fmaf(ssel[r][k], W_lab[k * TAGS + tag], a);
        slab[r][tag] = a;
    }
    __syncthreads();

    // ---- Label log-softmax: warp w handles row r = w ----
    {
        const int r = w;
        float m = -INFINITY;
        for (int tg = lane; tg < TAGS; tg += 32) m = fmaxf(m, slab[r][tg]);
        #pragma unroll
        for (int off = 16; off; off >>= 1)
            m = fmaxf(m, __shfl_xor_sync(0xffffffffu, m, off));
        float s = 0.f;
        for (int tg = lane; tg < TAGS; tg += 32) s += expf(slab[r][tg] - m);
        #pragma unroll
        for (int off = 16; off; off >>= 1)
            s += __shfl_xor_sync(0xffffffffu, s, off);
        const float lse = m + logf(s);
        const int tl = dlabs[b * LL + i0 + r];
        const float lab_ce = lse - slab[r][tl];

        if (lane == 0) {
            const int i = i0 + r;
            g_ce[b * LL + i] = (i < len) ? (arc_ce + lab_ce) : 0.f;
        }
    }
}

// ---------------------------------------------------------------------------
// Kernel 3: final reduction -> scalar loss
// ---------------------------------------------------------------------------
__global__ __launch_bounds__(256) void k3_reduce(
    const int* __restrict__ slen, float* __restrict__ out)
{
    __shared__ float red[256];
    float s = 0.f;
    for (int i = threadIdx.x; i < BB * LL; i += 256) s += g_ce[i];
    red[threadIdx.x] = s;
    __syncthreads();
    #pragma unroll
    for (int st = 128; st > 0; st >>= 1) {
        if (threadIdx.x < st) red[threadIdx.x] += red[threadIdx.x + st];
        __syncthreads();
    }
    if (threadIdx.x == 0) {
        float denom = 0.f;
        #pragma unroll
        for (int bb = 0; bb < BB; bb++) denom += (float)slen[bb];
        denom = fmaxf(denom, 1.f);
        out[0] = red[0] / denom * 0.5f;
    }
}

// ---------------------------------------------------------------------------
// Input order (metadata.txt):
// 0 contextualized [B,L,D] f32     1 sentence_lengths [B] i32
// 2 desired_arcs [B,L] i32         3 desired_labels [B,L] i32
// 4 W1 [D,H] f32                   5 b1 [H] f32
// 6 root [H] f32                   7 Wp [2H,H] f32
// 8 bp [H] f32                     9 W_arc [H,1] f32
// 10 b_arc [1] f32                 11 W_lab [H,TAGS] f32
// 12 b_lab [TAGS] f32
// ---------------------------------------------------------------------------
extern "C" void kernel_launch(void* const* d_in, const int* in_sizes, int n_in,
                              void* d_out, int out_size)
{
    const float* x     = (const float*)d_in[0];
    const int*   slen  = (const int*)  d_in[1];
    const int*   darcs = (const int*)  d_in[2];
    const int*   dlabs = (const int*)  d_in[3];
    const float* W1    = (const float*)d_in[4];
    const float* b1    = (const float*)d_in[5];
    const float* root  = (const float*)d_in[6];
    const float* Wp    = (const float*)d_in[7];
    const float* bp    = (const float*)d_in[8];
    const float* W_arc = (const float*)d_in[9];
    const float* W_lab = (const float*)d_in[11];
    const float* b_lab = (const float*)d_in[12];
    float* out = (float*)d_out;

    k1_proj <<< (BB * LL) / TM + 1, 256 >>>(x, W1, b1, root, Wp);
    k2_score<<< BB * (LL / GI),     256 >>>(slen, darcs, dlabs, bp, W_arc, W_lab, b_lab);
    k3_reduce<<< 1,                 256 >>>(slen, out);
}

// round 13
// speedup vs baseline: 1.0052x; 1.0048x over previous
#include <cuda_runtime.h>
#include <cuda_bf16.h>
#include <math.h>

// Problem constants
#define BB    16
#define LL    128
#define DD    512
#define HH    256
#define TAGS  45
#define LP1   129   // L + 1 (root prepended)

#define TM    8     // rows per block in kernel 1
#define GI    8     // i-rows per block in kernel 2

typedef unsigned long long ull;

// Scratch (device globals — no allocation allowed)
__device__ float g_ha[BB * LL * HH];     // hidden @ Wa           (2 MB)
__device__ float g_hb[BB * LL * HH];     // hidden @ Wb           (2 MB)
__device__ float g_hbroot[HH];           // root @ Wb
__device__ float g_ce[BB * LL];          // per-token (arc_ce + lab_ce) * mask

// ---- packed f32x2 helpers (sm_103a FFMA2 path, PTX-only) --------------------
__device__ __forceinline__ ull pack2(float lo, float hi) {
    ull r;
    asm("mov.b64 %0, {%1, %2};" : "=l"(r) : "f"(lo), "f"(hi));
    return r;
}
__device__ __forceinline__ void fma2(ull& d, ull a, ull b) {
    asm("fma.rn.f32x2 %0, %1, %2, %0;" : "+l"(d) : "l"(a), "l"(b));
}
__device__ __forceinline__ float hsum2(ull v) {
    float lo, hi;
    asm("mov.b64 {%0, %1}, %2;" : "=f"(lo), "=f"(hi) : "l"(v));
    return lo + hi;
}

// ---------------------------------------------------------------------------
// Kernel 1: hidden = relu(X @ W1 + b1); ha = hidden @ Wa; hb = hidden @ Wb
// Thread layout: tid = rh*128 + cp.  cp -> column pair (h0 = 2*cp), rh -> row
// half (rows rh*4 .. rh*4+3).  All threads of a row-half read the SAME smem
// x/h vector (broadcast), weights via coalesced LDG.64, accumulation in
// packed f32x2 along the K dimension (even/odd partial sums, hadd at end).
// Block 256 (last) computes g_hbroot = root @ Wb.
// ---------------------------------------------------------------------------
__global__ __launch_bounds__(256) void k1_proj(
    const float* __restrict__ x,     // [B,L,D]
    const float* __restrict__ W1,    // [D,H]
    const float* __restrict__ b1,    // [H]
    const float* __restrict__ root,  // [H]
    const float* __restrict__ Wp)    // [2H,H]
{
    if (blockIdx.x == (BB * LL) / TM) {
        const int h = threadIdx.x;
        float acc = 0.f;
        #pragma unroll 4
        for (int k = 0; k < HH; k++)
            acc = fmaf(root[k], Wp[(HH + k) * HH + h], acc);
        g_hbroot[h] = acc;
        return;
    }

    __shared__ __align__(16) float xs[TM][DD];   // 16 KB
    __shared__ __align__(16) float hs[TM][HH];   // 8 KB

    const int tid = threadIdx.x;
    const int cp  = tid & 127;        // column pair index 0..127
    const int rh  = tid >> 7;         // row half 0/1
    const int h0  = cp * 2;
    const int r0  = rh * 4;
    const int row0 = blockIdx.x * TM;

    // Load X tile (coalesced float4)
    {
        const float4* xg = reinterpret_cast<const float4*>(x + (size_t)row0 * DD);
        float4* xsv = reinterpret_cast<float4*>(&xs[0][0]);
        #pragma unroll
        for (int i = tid; i < TM * DD / 4; i += 256)
            xsv[i] = xg[i];
    }
    __syncthreads();

    // ---- Stage 1: hidden = relu(X @ W1 + b1), cols (h0, h0+1), rows r0..r0+3
    {
        const float2* w1v = reinterpret_cast<const float2*>(W1) + (h0 >> 1);
        ull acc[4][2];
        #pragma unroll
        for (int r = 0; r < 4; r++) { acc[r][0] = 0ull; acc[r][1] = 0ull; }

        #pragma unroll 2
        for (int d = 0; d < DD; d += 4) {
            const float2 w0 = w1v[(d + 0) * (HH / 2)];
            const float2 w1 = w1v[(d + 1) * (HH / 2)];
            const float2 w2 = w1v[(d + 2) * (HH / 2)];
            const float2 w3 = w1v[(d + 3) * (HH / 2)];
            const ull pc0_01 = pack2(w0.x, w1.x);   // col0, d-pair (d, d+1)
            const ull pc1_01 = pack2(w0.y, w1.y);   // col1
            const ull pc0_23 = pack2(w2.x, w3.x);
            const ull pc1_23 = pack2(w2.y, w3.y);
            #pragma unroll
            for (int r = 0; r < 4; r++) {
                const float4 xv = *reinterpret_cast<const float4*>(&xs[r0 + r][d]);
                const ull x01 = pack2(xv.x, xv.y);
                const ull x23 = pack2(xv.z, xv.w);
                fma2(acc[r][0], x01, pc0_01);
                fma2(acc[r][1], x01, pc1_01);
                fma2(acc[r][0], x23, pc0_23);
                fma2(acc[r][1], x23, pc1_23);
            }
        }
        const float bias0 = b1[h0];
        const float bias1 = b1[h0 + 1];
        #pragma unroll
        for (int r = 0; r < 4; r++) {
            float2 hv;
            hv.x = fmaxf(hsum2(acc[r][0]) + bias0, 0.f);
            hv.y = fmaxf(hsum2(acc[r][1]) + bias1, 0.f);
            *reinterpret_cast<float2*>(&hs[r0 + r][h0]) = hv;
        }
    }
    __syncthreads();

    // ---- Stage 2: ha = hidden @ Wa, hb = hidden @ Wb (same thread mapping)
    {
        const float2* wav = reinterpret_cast<const float2*>(Wp) + (h0 >> 1);
        const float2* wbv = reinterpret_cast<const float2*>(Wp + (size_t)HH * HH) + (h0 >> 1);

        ull aa[4][2], ab[4][2];
        #pragma unroll
        for (int r = 0; r < 4; r++) {
            aa[r][0] = 0ull; aa[r][1] = 0ull;
            ab[r][0] = 0ull; ab[r][1] = 0ull;
        }

        for (int k = 0; k < HH; k += 4) {
            const float2 a0 = wav[(k + 0) * (HH / 2)];
            const float2 a1 = wav[(k + 1) * (HH / 2)];
            const float2 a2 = wav[(k + 2) * (HH / 2)];
            const float2 a3 = wav[(k + 3) * (HH / 2)];
            const float2 b0 = wbv[(k + 0) * (HH / 2)];
            const float2 b1v = wbv[(k + 1) * (HH / 2)];
            const float2 b2 = wbv[(k + 2) * (HH / 2)];
            const float2 b3 = wbv[(k + 3) * (HH / 2)];

            const ull pa0_01 = pack2(a0.x, a1.x);
            const ull pa1_01 = pack2(a0.y, a1.y);
            const ull pa0_23 = pack2(a2.x, a3.x);
            const ull pa1_23 = pack2(a2.y, a3.y);
            const ull pb0_01 = pack2(b0.x, b1v.x);
            const ull pb1_01 = pack2(b0.y, b1v.y);
            const ull pb0_23 = pack2(b2.x, b3.x);
            const ull pb1_23 = pack2(b2.y, b3.y);

            #pragma unroll
            for (int r = 0; r < 4; r++) {
                const float4 hv = *reinterpret_cast<const float4*>(&hs[r0 + r][k]);
                const ull h01 = pack2(hv.x, hv.y);
                const ull h23 = pack2(hv.z, hv.w);
                fma2(aa[r][0], h01, pa0_01);
                fma2(aa[r][1], h01, pa1_01);
                fma2(aa[r][0], h23, pa0_23);
                fma2(aa[r][1], h23, pa1_23);
                fma2(ab[r][0], h01, pb0_01);
                fma2(ab[r][1], h01, pb1_01);
                fma2(ab[r][0], h23, pb0_23);
                fma2(ab[r][1], h23, pb1_23);
            }
        }

        #pragma unroll
        for (int r = 0; r < 4; r++) {
            const size_t row = (size_t)(row0 + r0 + r);
            float2 va, vb;
            va.x = hsum2(aa[r][0]);  va.y = hsum2(aa[r][1]);
            vb.x = hsum2(ab[r][0]);  vb.y = hsum2(ab[r][1]);
            *reinterpret_cast<float2*>(&g_ha[row * HH + h0]) = va;
            *reinterpret_cast<float2*>(&g_hb[row * HH + h0]) = vb;
        }
    }
}

// ---------------------------------------------------------------------------
// Kernel 2: for each (b, i): arc logits over j=0..128 (computed on the fly),
// arc log-softmax CE; gathered sel = relu(ha_i + hb_{j*} + bp); label logits,
// label log-softmax CE. Writes g_ce[b*L+i] = mask * (arc_ce + lab_ce).
// One block per (b, group of GI=8 i-rows). 256 threads = 8 warps.
// ---------------------------------------------------------------------------
__global__ __launch_bounds__(256) void k2_score(
    const int*   __restrict__ slen,     // [B]
    const int*   __restrict__ darcs,    // [B,L]
    const int*   __restrict__ dlabs,    // [B,L]
    const float* __restrict__ bp,       // [H]
    const float* __restrict__ W_arc,    // [H,1]
    const float* __restrict__ W_lab,    // [H,TAGS]
    const float* __restrict__ b_lab)    // [TAGS]
{
    __shared__ float sha[GI][HH];        // ha rows + bp   (8 KB)
    __shared__ float warc[HH];           // 1 KB
    __shared__ float slog[GI][132];      // arc logits     (~4.2 KB)
    __shared__ float ssel[GI][HH];       // gathered pair repr (8 KB)
    __shared__ float slab[GI][48];       // label logits   (1.5 KB)

    const int t    = threadIdx.x;
    const int w    = t >> 5;
    const int lane = t & 31;

    const int b  = blockIdx.x / (LL / GI);
    const int ig = blockIdx.x % (LL / GI);
    const int i0 = ig * GI;
    const int len = slen[b];

    // Load ha rows (+bp) and W_arc
    warc[t] = W_arc[t];
    #pragma unroll
    for (int r = 0; r < GI; r++)
        sha[r][t] = g_ha[(size_t)(b * LL + i0 + r) * HH + t] + bp[t];
    __syncthreads();

    // ---- Arc logits: warp w handles j = w, w+8, ... ----
    for (int j = w; j < LP1; j += 8) {
        const float* hbj = (j == 0) ? g_hbroot
                                    : &g_hb[(size_t)(b * LL + (j - 1)) * HH];
        float p[GI];
        #pragma unroll
        for (int r = 0; r < GI; r++) p[r] = 0.f;

        #pragma unroll
        for (int t8 = 0; t8 < 8; t8++) {
            const int k = lane + 32 * t8;
            const float hv = hbj[k];
            const float wv = warc[k];
            #pragma unroll
            for (int r = 0; r < GI; r++)
                p[r] = fmaf(fmaxf(sha[r][k] + hv, 0.f), wv, p[r]);
        }
        #pragma unroll
        for (int r = 0; r < GI; r++) {
            float v = p[r];
            #pragma unroll
            for (int off = 16; off; off >>= 1)
                v += __shfl_xor_sync(0xffffffffu, v, off);
            p[r] = v;
        }
        if (lane == 0) {
            #pragma unroll
            for (int r = 0; r < GI; r++) slog[r][j] = p[r];
        }
    }
    __syncthreads();

    // ---- Arc log-softmax: warp w handles row r = w ----
    float arc_ce = 0.f;
    {
        const int r = w;
        float m = -INFINITY;
        for (int jj = lane; jj < LP1; jj += 32) m = fmaxf(m, slog[r][jj]);
        #pragma unroll
        for (int off = 16; off; off >>= 1)
            m = fmaxf(m, __shfl_xor_sync(0xffffffffu, m, off));
        float s = 0.f;
        for (int jj = lane; jj < LP1; jj += 32) s += expf(slog[r][jj] - m);
        #pragma unroll
        for (int off = 16; off; off >>= 1)
            s += __shfl_xor_sync(0xffffffffu, s, off);
        const float lse = m + logf(s);
        const int ja = darcs[b * LL + i0 + r];
        arc_ce = lse - slog[r][ja];
    }

    // ---- Gathered sel = relu(ha + hb[j*] + bp), all threads ----
    #pragma unroll
    for (int r = 0; r < GI; r++) {
        const int ja = darcs[b * LL + i0 + r];
        const float* hbj = (ja == 0) ? g_hbroot
                                     : &g_hb[(size_t)(b * LL + (ja - 1)) * HH];
        ssel[r][t] = fmaxf(sha[r][t] + hbj[t], 0.f);
    }
    __syncthreads();

    // ---- Label logits: 360 dots of length 256 spread over threads ----
    for (int q = t; q < GI * TAGS; q += 256) {
        const int r = q / TAGS;
        const int tag = q % TAGS;
        float a = b_lab[tag];
        #pragma unroll 4
        for (int k = 0; k < HH; k++)
            a = fmaf(ssel[r][k], W_lab[k * TAGS + tag], a);
        slab[r][tag] = a;
    }
    __syncthreads();

    // ---- Label log-softmax: warp w handles row r = w ----
    {
        const int r = w;
        float m = -INFINITY;
        for (int tg = lane; tg < TAGS; tg += 32) m = fmaxf(m, slab[r][tg]);
        #pragma unroll
        for (int off = 16; off; off >>= 1)
            m = fmaxf(m, __shfl_xor_sync(0xffffffffu, m, off));
        float s = 0.f;
        for (int tg = lane; tg < TAGS; tg += 32) s += expf(slab[r][tg] - m);
        #pragma unroll
        for (int off = 16; off; off >>= 1)
            s += __shfl_xor_sync(0xffffffffu, s, off);
        const float lse = m + logf(s);
        const int tl = dlabs[b * LL + i0 + r];
        const float lab_ce = lse - slab[r][tl];

        if (lane == 0) {
            const int i = i0 + r;
            g_ce[b * LL + i] = (i < len) ? (arc_ce + lab_ce) : 0.f;
        }
    }
}

// ---------------------------------------------------------------------------
// Kernel 3: final reduction -> scalar loss
// ---------------------------------------------------------------------------
__global__ __launch_bounds__(256) void k3_reduce(
    const int* __restrict__ slen, float* __restrict__ out)
{
    __shared__ float red[256];
    float s = 0.f;
    for (int i = threadIdx.x; i < BB * LL; i += 256) s += g_ce[i];
    red[threadIdx.x] = s;
    __syncthreads();
    #pragma unroll
    for (int st = 128; st > 0; st >>= 1) {
        if (threadIdx.x < st) red[threadIdx.x] += red[threadIdx.x + st];
        __syncthreads();
    }
    if (threadIdx.x == 0) {
        float denom = 0.f;
        #pragma unroll
        for (int bb = 0; bb < BB; bb++) denom += (float)slen[bb];
        denom = fmaxf(denom, 1.f);
        out[0] = red[0] / denom * 0.5f;
    }
}

// ---------------------------------------------------------------------------
// Input order (metadata.txt):
// 0 contextualized [B,L,D] f32     1 sentence_lengths [B] i32
// 2 desired_arcs [B,L] i32         3 desired_labels [B,L] i32
// 4 W1 [D,H] f32                   5 b1 [H] f32
// 6 root [H] f32                   7 Wp [2H,H] f32
// 8 bp [H] f32                     9 W_arc [H,1] f32
// 10 b_arc [1] f32                 11 W_lab [H,TAGS] f32
// 12 b_lab [TAGS] f32
// ---------------------------------------------------------------------------
extern "C" void kernel_launch(void* const* d_in, const int* in_sizes, int n_in,
                              void* d_out, int out_size)
{
    const float* x     = (const float*)d_in[0];
    const int*   slen  = (const int*)  d_in[1];
    const int*   darcs = (const int*)  d_in[2];
    const int*   dlabs = (const int*)  d_in[3];
    const float* W1    = (const float*)d_in[4];
    const float* b1    = (const float*)d_in[5];
    const float* root  = (const float*)d_in[6];
    const float* Wp    = (const float*)d_in[7];
    const float* bp    = (const float*)d_in[8];
    const float* W_arc = (const float*)d_in[9];
    const float* W_lab = (const float*)d_in[11];
    const float* b_lab = (const float*)d_in[12];
    float* out = (float*)d_out;

    k1_proj <<< (BB * LL) / TM + 1, 256 >>>(x, W1, b1, root, Wp);
    k2_score<<< BB * (LL / GI),     256 >>>(slen, darcs, dlabs, bp, W_arc, W_lab, b_lab);
    k3_reduce<<< 1,                 256 >>>(slen, out);
}